// round 3
// baseline (speedup 1.0000x reference)
#include <cuda_runtime.h>

// metaCLF fused kernel: per-voxel
//   e_axis = W2 @ relu(W1 @ d_pair)        (3x, each 2->16->3)
//   enc    = kron(kron(e_x, e_y), e_z)     (27)
//   h      = relu(G1 @ enc)                (32)
//   h2_k   = relu(G2[k,:] @ h)             (64, computed on the fly)
//   out    = sum_k h2_k * (G3[:,k] . x)    (avoids materializing filters)
//
// Two consecutive voxels per thread, all math in packed fp32x2 (sm_10x
// fma.rn.f32x2 / mul.rn.f32x2 / add.rn.f32x2). Weights pre-packed {w,w}
// into shared memory once per block; inner loops read them via broadcast
// LDS.64 (conflict-free, uniform address).

typedef unsigned long long u64;

#define HWD   (96*96*96)   // 884736
#define NPAIR (HWD/2)      // 442368
#define NB    2

__device__ __forceinline__ u64 bc2(float w) {
    u64 r; asm("mov.b64 %0, {%1, %2};" : "=l"(r) : "f"(w), "f"(w)); return r;
}
__device__ __forceinline__ u64 fma2(u64 a, u64 b, u64 c) {
    u64 d; asm("fma.rn.f32x2 %0, %1, %2, %3;" : "=l"(d) : "l"(a), "l"(b), "l"(c)); return d;
}
__device__ __forceinline__ u64 mul2(u64 a, u64 b) {
    u64 d; asm("mul.rn.f32x2 %0, %1, %2;" : "=l"(d) : "l"(a), "l"(b)); return d;
}
__device__ __forceinline__ u64 add2(u64 a, u64 b) {
    u64 d; asm("add.rn.f32x2 %0, %1, %2;" : "=l"(d) : "l"(a), "l"(b)); return d;
}
__device__ __forceinline__ u64 relu2(u64 a) {
    float lo, hi;
    asm("mov.b64 {%0, %1}, %2;" : "=f"(lo), "=f"(hi) : "l"(a));
    lo = fmaxf(lo, 0.0f); hi = fmaxf(hi, 0.0f);
    u64 r; asm("mov.b64 %0, {%1, %2};" : "=l"(r) : "f"(lo), "f"(hi));
    return r;
}

__global__ void __launch_bounds__(128)
metaCLF_kernel(const float* __restrict__ x, const float* __restrict__ d_all,
               const float* __restrict__ W1, const float* __restrict__ W2,
               const float* __restrict__ G1, const float* __restrict__ G2,
               const float* __restrict__ G3, float* __restrict__ out)
{
    // ---- stage packed weights into shared memory ----
    // layout: W1[32] @0, W2[48] @32, G1[864] @80, G2[2048] @944, G3[2048] @2992
    __shared__ u64 sw[5040];
    {
        const int t = threadIdx.x;
        for (int i = t; i < 32;   i += 128) sw[i]        = bc2(W1[i]);
        for (int i = t; i < 48;   i += 128) sw[32 + i]   = bc2(W2[i]);
        for (int i = t; i < 864;  i += 128) sw[80 + i]   = bc2(G1[i]);
        for (int i = t; i < 2048; i += 128) sw[944 + i]  = bc2(G2[i]);
        for (int i = t; i < 2048; i += 128) sw[2992 + i] = bc2(G3[i]);
    }
    __syncthreads();
    const u64* sW1 = sw;
    const u64* sW2 = sw + 32;
    const u64* sG1 = sw + 80;
    const u64* sG2 = sw + 944;
    const u64* sG3 = sw + 2992;

    const int g = blockIdx.x * 128 + threadIdx.x;   // pair index, exact grid
    const int b = g / NPAIR;
    const long long v = (long long)(g - b * NPAIR) * 2;

    // ---- encode: e[axis][o] = W2 @ relu(W1 @ d_pair) ----
    const float* db = d_all + (long long)b * 6 * HWD + v;
    u64 e[3][3];
#pragma unroll
    for (int a = 0; a < 3; ++a) {
        const u64 d0 = *(const u64*)(db + (long long)(2 * a + 0) * HWD);
        const u64 d1 = *(const u64*)(db + (long long)(2 * a + 1) * HWD);
        u64 a0, a1, a2;
#pragma unroll
        for (int j = 0; j < 16; ++j) {
            u64 t = fma2(sW1[2 * j], d0, mul2(sW1[2 * j + 1], d1));
            t = relu2(t);
            if (j == 0) {
                a0 = mul2(sW2[0 * 16 + j], t);
                a1 = mul2(sW2[1 * 16 + j], t);
                a2 = mul2(sW2[2 * 16 + j], t);
            } else {
                a0 = fma2(sW2[0 * 16 + j], t, a0);
                a1 = fma2(sW2[1 * 16 + j], t, a1);
                a2 = fma2(sW2[2 * 16 + j], t, a2);
            }
        }
        e[a][0] = a0; e[a][1] = a1; e[a][2] = a2;
    }

    // ---- kron: enc[(i*3+j)*3+k] = e_x[i]*e_y[j]*e_z[k] ----
    u64 enc[27];
#pragma unroll
    for (int i = 0; i < 3; ++i)
#pragma unroll
        for (int j = 0; j < 3; ++j) {
            const u64 pij = mul2(e[0][i], e[1][j]);
#pragma unroll
            for (int k = 0; k < 3; ++k)
                enc[(i * 3 + j) * 3 + k] = mul2(pij, e[2][k]);
        }

    // ---- h = relu(G1 @ enc) ----
    u64 h[32];
#pragma unroll
    for (int c = 0; c < 32; ++c) h[c] = mul2(sG1[c * 27], enc[0]);
#pragma unroll 2
    for (int eIdx = 1; eIdx < 27; ++eIdx) {
        const u64 ev = enc[eIdx];
#pragma unroll
        for (int c = 0; c < 32; ++c)
            h[c] = fma2(sG1[c * 27 + eIdx], ev, h[c]);
    }
#pragma unroll
    for (int c = 0; c < 32; ++c) h[c] = relu2(h[c]);

    // ---- load x (packed pair per channel) ----
    const float* xb = x + (long long)b * 32 * HWD + v;
    u64 xr[32];
#pragma unroll
    for (int c = 0; c < 32; ++c)
        xr[c] = *(const u64*)(xb + (long long)c * HWD);

    // ---- out = sum_k relu(G2[k,:]@h) * (G3[:,k] . x) ----
    u64 acc = 0;   // +0.0f packed
#pragma unroll 1
    for (int k = 0; k < 64; ++k) {
        const u64* g2 = sG2 + k * 32;
        u64 s0 = mul2(g2[0], h[0]);
        u64 s1 = mul2(g2[1], h[1]);
#pragma unroll
        for (int c = 2; c < 32; c += 2) {
            s0 = fma2(g2[c],     h[c],     s0);
            s1 = fma2(g2[c + 1], h[c + 1], s1);
        }
        const u64 hk = relu2(add2(s0, s1));

        u64 t0 = mul2(sG3[0 * 64 + k], xr[0]);
        u64 t1 = mul2(sG3[1 * 64 + k], xr[1]);
#pragma unroll
        for (int c = 2; c < 32; c += 2) {
            t0 = fma2(sG3[c * 64 + k],       xr[c],     t0);
            t1 = fma2(sG3[(c + 1) * 64 + k], xr[c + 1], t1);
        }
        acc = fma2(hk, add2(t0, t1), acc);
    }

    *(u64*)(out + (long long)b * HWD + v) = acc;
}

extern "C" void kernel_launch(void* const* d_in, const int* in_sizes, int n_in,
                              void* d_out, int out_size)
{
    const float* x    = (const float*)d_in[0];
    const float* dall = (const float*)d_in[1];
    const float* W1   = (const float*)d_in[2];
    const float* W2   = (const float*)d_in[3];
    const float* G1   = (const float*)d_in[4];
    const float* G2   = (const float*)d_in[5];
    const float* G3   = (const float*)d_in[6];
    float* out = (float*)d_out;

    const int total_threads = NB * NPAIR;          // 884736, divisible by 128
    dim3 grid(total_threads / 128);
    metaCLF_kernel<<<grid, 128>>>(x, dall, W1, W2, G1, G2, G3, out);
}

// round 4
// speedup vs baseline: 1.0710x; 1.0710x over previous
#include <cuda_runtime.h>

// metaCLF fused kernel, R3: packed fp32x2 math + 128-bit shared weight loads.
//
// R2 post-mortem showed the kernel LSU-bound (L1TEX 72.8%, fma 37%): one
// LDS.64 per FFMA2. This round every weight fetch is ld.shared.v2.b64
// (one LDS.128 feeds two FFMA2s), with padded/transposed smem layouts:
//   sW1  [32]        pairs (2j,2j+1) -> v2
//   sW2t [16][4]     transposed+padded W2 -> v2 + scalar
//   sG1p [32][28]    rows padded 27->28 -> 14 v2/row (enc28[27]=0)
//   sG2  [64][32]    already row-contiguous -> 16 v2/row
//   sG3t [64][32]    transposed G3 -> 16 v2/row
// __launch_bounds__(128,3) caps regs for 3 blocks/SM (12 warps).

typedef unsigned long long u64;

#define HWD   (96*96*96)   // 884736
#define NPAIR (HWD/2)      // 442368
#define NB    2

// smem layout offsets (in u64 units)
#define OFF_W1   0
#define OFF_W2T  32
#define OFF_G1P  96
#define OFF_G2   992
#define OFF_G3T  3040
#define SW_TOTAL 5088

__device__ __forceinline__ u64 bc2(float w) {
    u64 r; asm("mov.b64 %0, {%1, %2};" : "=l"(r) : "f"(w), "f"(w)); return r;
}
__device__ __forceinline__ u64 fma2(u64 a, u64 b, u64 c) {
    u64 d; asm("fma.rn.f32x2 %0, %1, %2, %3;" : "=l"(d) : "l"(a), "l"(b), "l"(c)); return d;
}
__device__ __forceinline__ u64 mul2(u64 a, u64 b) {
    u64 d; asm("mul.rn.f32x2 %0, %1, %2;" : "=l"(d) : "l"(a), "l"(b)); return d;
}
__device__ __forceinline__ u64 add2(u64 a, u64 b) {
    u64 d; asm("add.rn.f32x2 %0, %1, %2;" : "=l"(d) : "l"(a), "l"(b)); return d;
}
__device__ __forceinline__ u64 relu2(u64 a) {
    float lo, hi;
    asm("mov.b64 {%0, %1}, %2;" : "=f"(lo), "=f"(hi) : "l"(a));
    lo = fmaxf(lo, 0.0f); hi = fmaxf(hi, 0.0f);
    u64 r; asm("mov.b64 %0, {%1, %2};" : "=l"(r) : "f"(lo), "f"(hi));
    return r;
}
// 128-bit shared load: one LDS.128 returning two packed weights.
__device__ __forceinline__ void lds2(const u64* p, u64& a, u64& b) {
    unsigned long long sp = __cvta_generic_to_shared(p);
    asm("ld.shared.v2.b64 {%0, %1}, [%2];" : "=l"(a), "=l"(b) : "l"(sp));
}

__global__ void __launch_bounds__(128, 3)
metaCLF_kernel(const float* __restrict__ x, const float* __restrict__ d_all,
               const float* __restrict__ W1, const float* __restrict__ W2,
               const float* __restrict__ G1, const float* __restrict__ G2,
               const float* __restrict__ G3, float* __restrict__ out)
{
    __shared__ __align__(16) u64 sw[SW_TOTAL];
    {
        const int t = threadIdx.x;
        for (int i = t; i < 32; i += 128) sw[OFF_W1 + i] = bc2(W1[i]);
        for (int i = t; i < 64; i += 128) {
            int j = i >> 2, o = i & 3;
            sw[OFF_W2T + i] = (o < 3) ? bc2(W2[o * 16 + j]) : 0ull;
        }
        for (int i = t; i < 896; i += 128) {
            int c = i / 28, e = i - c * 28;
            sw[OFF_G1P + i] = (e < 27) ? bc2(G1[c * 27 + e]) : 0ull;
        }
        for (int i = t; i < 2048; i += 128) sw[OFF_G2 + i] = bc2(G2[i]);
        for (int i = t; i < 2048; i += 128) {
            int k = i >> 5, c = i & 31;
            sw[OFF_G3T + i] = bc2(G3[c * 64 + k]);
        }
    }
    __syncthreads();
    const u64* sW1  = sw + OFF_W1;
    const u64* sW2t = sw + OFF_W2T;
    const u64* sG1p = sw + OFF_G1P;
    const u64* sG2  = sw + OFF_G2;
    const u64* sG3t = sw + OFF_G3T;

    const int g = blockIdx.x * 128 + threadIdx.x;   // pair index, exact grid
    const int b = g / NPAIR;
    const long long v = (long long)(g - b * NPAIR) * 2;

    // ---- encode: e[axis][o] = W2 @ relu(W1 @ d_pair) ----
    const float* db = d_all + (long long)b * 6 * HWD + v;
    u64 e[3][3];
#pragma unroll
    for (int a = 0; a < 3; ++a) {
        const u64 d0 = *(const u64*)(db + (long long)(2 * a + 0) * HWD);
        const u64 d1 = *(const u64*)(db + (long long)(2 * a + 1) * HWD);
        u64 a0, a1, a2;
#pragma unroll
        for (int j = 0; j < 16; ++j) {
            u64 w10, w11;
            lds2(sW1 + 2 * j, w10, w11);               // W1[j][0], W1[j][1]
            u64 t = fma2(w10, d0, mul2(w11, d1));
            t = relu2(t);
            u64 w20, w21;
            lds2(sW2t + 4 * j, w20, w21);              // W2[0][j], W2[1][j]
            const u64 w22 = sW2t[4 * j + 2];           // W2[2][j]
            if (j == 0) {
                a0 = mul2(w20, t);
                a1 = mul2(w21, t);
                a2 = mul2(w22, t);
            } else {
                a0 = fma2(w20, t, a0);
                a1 = fma2(w21, t, a1);
                a2 = fma2(w22, t, a2);
            }
        }
        e[a][0] = a0; e[a][1] = a1; e[a][2] = a2;
    }

    // ---- kron -> enc28 (padded with zero at [27]) ----
    u64 enc28[28];
#pragma unroll
    for (int i = 0; i < 3; ++i)
#pragma unroll
        for (int j = 0; j < 3; ++j) {
            const u64 pij = mul2(e[0][i], e[1][j]);
#pragma unroll
            for (int k = 0; k < 3; ++k)
                enc28[(i * 3 + j) * 3 + k] = mul2(pij, e[2][k]);
        }
    enc28[27] = 0ull;

    // ---- h = relu(G1 @ enc), row-contiguous v2 loads ----
    u64 h[32];
#pragma unroll 4
    for (int c = 0; c < 32; ++c) {
        const u64* row = sG1p + c * 28;
        u64 w0, w1;
        lds2(row, w0, w1);
        u64 a0 = mul2(w0, enc28[0]);
        u64 a1 = mul2(w1, enc28[1]);
#pragma unroll
        for (int eI = 2; eI < 28; eI += 2) {
            lds2(row + eI, w0, w1);
            a0 = fma2(w0, enc28[eI],     a0);
            a1 = fma2(w1, enc28[eI + 1], a1);
        }
        h[c] = relu2(add2(a0, a1));
    }

    // ---- load x (packed pair per channel) ----
    const float* xb = x + (long long)b * 32 * HWD + v;
    u64 xr[32];
#pragma unroll
    for (int c = 0; c < 32; ++c)
        xr[c] = *(const u64*)(xb + (long long)c * HWD);

    // ---- out = sum_k relu(G2[k,:]@h) * (G3t[k,:] . x) ----
    u64 acc = 0ull;
#pragma unroll 2
    for (int k = 0; k < 64; ++k) {
        const u64* g2 = sG2  + k * 32;
        const u64* g3 = sG3t + k * 32;
        u64 w0, w1, u0, u1;
        lds2(g2, w0, w1);
        lds2(g3, u0, u1);
        u64 s0 = mul2(w0, h[0]);
        u64 s1 = mul2(w1, h[1]);
        u64 t0 = mul2(u0, xr[0]);
        u64 t1 = mul2(u1, xr[1]);
#pragma unroll
        for (int c = 2; c < 32; c += 2) {
            lds2(g2 + c, w0, w1);
            s0 = fma2(w0, h[c],     s0);
            s1 = fma2(w1, h[c + 1], s1);
            lds2(g3 + c, u0, u1);
            t0 = fma2(u0, xr[c],     t0);
            t1 = fma2(u1, xr[c + 1], t1);
        }
        const u64 hk = relu2(add2(s0, s1));
        acc = fma2(hk, add2(t0, t1), acc);
    }

    *(u64*)(out + (long long)b * HWD + v) = acc;
}

extern "C" void kernel_launch(void* const* d_in, const int* in_sizes, int n_in,
                              void* d_out, int out_size)
{
    const float* x    = (const float*)d_in[0];
    const float* dall = (const float*)d_in[1];
    const float* W1   = (const float*)d_in[2];
    const float* W2   = (const float*)d_in[3];
    const float* G1   = (const float*)d_in[4];
    const float* G2   = (const float*)d_in[5];
    const float* G3   = (const float*)d_in[6];
    float* out = (float*)d_out;

    const int total_threads = NB * NPAIR;          // 884736, divisible by 128
    dim3 grid(total_threads / 128);
    metaCLF_kernel<<<grid, 128>>>(x, dall, W1, W2, G1, G2, G3, out);
}